// round 1
// baseline (speedup 1.0000x reference)
#include <cuda_runtime.h>
#include <math.h>
#include <float.h>

#define N_ROWS   8192
#define C_DIM    256
#define K_CODES  16384
#define OUT_EMB  2097152
#define BM       128

// ---------------- scratch (no allocations allowed) ----------------
__device__ __align__(16) float  g_zflat[N_ROWS * C_DIM];   // 8 MB, [n][c]
__device__ __align__(16) float  g_enorm[K_CODES];
__device__ float  g_pval[2 * N_ROWS];
__device__ int    g_pidx[2 * N_ROWS];
__device__ int    g_idx[N_ROWS];
__device__ int    g_hist[K_CODES];
__device__ double g_accum;

// ---------------- init ----------------
__global__ void init_kernel() {
    int t = blockIdx.x * blockDim.x + threadIdx.x;
    if (t < K_CODES) g_hist[t] = 0;
    if (t == 0) g_accum = 0.0;
}

// ---------------- z [B,C,T,H,W] -> z_flat [N, C] ----------------
__global__ void transpose_kernel(const float* __restrict__ z) {
    __shared__ float s[32][33];
    int n0 = blockIdx.x * 32, c0 = blockIdx.y * 32;
    int tx = threadIdx.x, ty = threadIdx.y;
#pragma unroll
    for (int k = 0; k < 4; k++) {
        int yy = ty + k * 8;
        int c = c0 + yy;
        int n = n0 + tx;
        int b = n >> 11, thw = n & 2047;
        s[yy][tx] = z[((b * C_DIM + c) << 11) + thw];
    }
    __syncthreads();
#pragma unroll
    for (int k = 0; k < 4; k++) {
        int yy = ty + k * 8;
        g_zflat[(n0 + yy) * C_DIM + c0 + tx] = s[tx][yy];
    }
}

// ---------------- ||e_k||^2 ----------------
__global__ void enorm_kernel(const float* __restrict__ emb) {
    int w = (blockIdx.x * blockDim.x + threadIdx.x) >> 5;
    int lane = threadIdx.x & 31;
    if (w >= K_CODES) return;
    const float4* e4 = (const float4*)(emb + (size_t)w * C_DIM);
    float s = 0.f;
#pragma unroll
    for (int q = 0; q < 2; q++) {
        float4 v = e4[q * 32 + lane];
        s += v.x * v.x + v.y * v.y + v.z * v.z + v.w * v.w;
    }
#pragma unroll
    for (int o = 16; o > 0; o >>= 1) s += __shfl_down_sync(0xffffffffu, s, o);
    if (lane == 0) g_enorm[w] = s;
}

// ---------------- fused distance GEMM + argmin ----------------
// grid (64 row-tiles, 2 code-splits), 256 threads.
// smem: A  = 128x256 fp32 (128 KB, swizzled, resident whole block)
//       B  = 2 x (64k x 128cols) fp32 (64 KB, double-buffered, swizzled)
__global__ void __launch_bounds__(256, 1)
vq_main(const float* __restrict__ emb) {
    extern __shared__ float sm[];
    float* As = sm;            // 32768 floats
    float* Bs = sm + 32768;    // 16384 floats

    const int tid = threadIdx.x;
    const int tx = tid & 15, ty = tid >> 4;
    const int m0 = blockIdx.x * BM;
    const int split = blockIdx.y;
    const int code_base_split = split * 8192;

    // ---- load A tile (rows m0..m0+127, all 256 k), swizzled ----
    {
        const float4* z4 = (const float4*)g_zflat;
#pragma unroll 4
        for (int q = 0; q < 32; q++) {
            int idx4 = q * 256 + tid;
            int m = idx4 >> 6;          // 0..127
            int k4 = idx4 & 63;         // float4 index along k
            float4 v = z4[(size_t)(m0 + m) * 64 + k4];
            int sw = k4 & 7;
            int base = (k4 * 4) * 128 + (((m >> 2) ^ sw) << 2) + (m & 3);
            As[base +   0] = v.x;
            As[base + 128] = v.y;
            As[base + 256] = v.z;
            As[base + 384] = v.w;
        }
    }

    float acc[8][8];
#pragma unroll
    for (int i = 0; i < 8; i++)
#pragma unroll
        for (int j = 0; j < 8; j++) acc[i][j] = 0.f;

    float best[8];
    int bidx[8];
#pragma unroll
    for (int i = 0; i < 8; i++) { best[i] = INFINITY; bidx[i] = 0; }

    const float4* e4 = (const float4*)emb;
    float4 rb[8];

    // slice t (0..255): chunk = t>>2 (128 codes), k-slice s = t&3 (64 k)
    auto loadB = [&](int t, float4* r) {
        int chunk = t >> 2, s = t & 3;
        int code0 = code_base_split + chunk * 128;
#pragma unroll
        for (int q = 0; q < 8; q++) {
            int idx4 = q * 256 + tid;
            int col = idx4 >> 4;       // 0..127
            int k4 = idx4 & 15;        // float4 within slice
            r[q] = e4[(size_t)(code0 + col) * 64 + s * 16 + k4];
        }
    };
    auto storeB = [&](int buf, float4* r) {
#pragma unroll
        for (int q = 0; q < 8; q++) {
            int idx4 = q * 256 + tid;
            int col = idx4 >> 4;
            int k4 = idx4 & 15;
            int base = buf * 8192 + (k4 * 4) * 128 +
                       (((col >> 2) ^ (k4 & 7)) << 2) + (col & 3);
            Bs[base +   0] = r[q].x;
            Bs[base + 128] = r[q].y;
            Bs[base + 256] = r[q].z;
            Bs[base + 384] = r[q].w;
        }
    };

    loadB(0, rb);
    storeB(0, rb);
    loadB(1, rb);
    __syncthreads();

    const float4* A4 = (const float4*)As;
    const float4* B4 = (const float4*)Bs;

    for (int t = 0; t < 256; t++) {
        const int buf = t & 1;
        const int kbase = (t & 3) * 64;       // global k offset of this slice
        const int bbase = buf * 2048;         // float4 offset of buffer

#pragma unroll 4
        for (int kk = 0; kk < 64; kk++) {
            int kg = kbase + kk;
            int swA = (kg >> 2) & 7;
            int swB = (kk >> 2) & 7;
            float4 a0 = A4[kg * 32 + ((2 * ty) ^ swA)];
            float4 a1 = A4[kg * 32 + ((2 * ty + 1) ^ swA)];
            float4 b0 = B4[bbase + kk * 32 + (tx ^ swB)];
            float4 b1 = B4[bbase + kk * 32 + 16 + (tx ^ swB)];
            float a[8] = {a0.x, a0.y, a0.z, a0.w, a1.x, a1.y, a1.z, a1.w};
            float b[8] = {b0.x, b0.y, b0.z, b0.w, b1.x, b1.y, b1.z, b1.w};
#pragma unroll
            for (int i = 0; i < 8; i++)
#pragma unroll
                for (int j = 0; j < 8; j++)
                    acc[i][j] = fmaf(a[i], b[j], acc[i][j]);
        }

        if ((t & 3) == 3) {
            // chunk epilogue: distance + running argmin, reset accumulators
            int code0 = code_base_split + (t >> 2) * 128;
#pragma unroll
            for (int j = 0; j < 8; j++) {
                int col = (j < 4) ? (tx * 4 + j) : (64 + tx * 4 + (j - 4));
                int code = code0 + col;
                float en = __ldg(&g_enorm[code]);
#pragma unroll
                for (int i = 0; i < 8; i++) {
                    float d = en - 2.0f * acc[i][j];
                    if (d < best[i]) { best[i] = d; bidx[i] = code; }
                    acc[i][j] = 0.f;
                }
            }
        }

        if (t + 1 < 256) {
            __syncthreads();
            storeB(buf ^ 1, rb);
            if (t + 2 < 256) loadB(t + 2, rb);
            __syncthreads();
        }
    }

    // ---- cross-thread argmin reduction (reuse B smem) ----
    __syncthreads();
    float* rv = Bs;                 // 2048 floats
    int* ri = (int*)(Bs + 2048);    // 2048 ints
#pragma unroll
    for (int i = 0; i < 8; i++) {
        int r = ty * 8 + i;
        rv[r * 16 + tx] = best[i];
        ri[r * 16 + tx] = bidx[i];
    }
    __syncthreads();
    if (tid < 128) {
        float bv = rv[tid * 16];
        int bi = ri[tid * 16];
#pragma unroll
        for (int x = 1; x < 16; x++) {
            float v = rv[tid * 16 + x];
            int id = ri[tid * 16 + x];
            if (v < bv || (v == bv && id < bi)) { bv = v; bi = id; }
        }
        g_pval[split * N_ROWS + m0 + tid] = bv;
        g_pidx[split * N_ROWS + m0 + tid] = bi;
    }
}

// ---------------- merge the 2 code-splits + histogram ----------------
__global__ void merge_kernel() {
    int n = blockIdx.x * blockDim.x + threadIdx.x;
    if (n >= N_ROWS) return;
    float v0 = g_pval[n];          int i0 = g_pidx[n];
    float v1 = g_pval[N_ROWS + n]; int i1 = g_pidx[N_ROWS + n];
    int bestv = (v1 < v0 || (v1 == v0 && i1 < i0)) ? i1 : i0;
    g_idx[n] = bestv;
    atomicAdd(&g_hist[bestv], 1);
}

// ---------------- gather + channels-first output + commitment loss ----
__global__ void out_kernel(const float* __restrict__ z,
                           const float* __restrict__ emb,
                           float* __restrict__ out) {
    int i = blockIdx.x * blockDim.x + threadIdx.x;   // 0 .. 2097151
    int b = i >> 19;
    int rem = i & 524287;
    int c = rem >> 11;
    int thw = rem & 2047;
    int n = (b << 11) | thw;
    int idx = g_idx[n];
    float e = emb[(size_t)idx * C_DIM + c];
    out[i] = e;
    if (c == 0) out[OUT_EMB + n] = (float)idx;
    float d = z[i] - e;
    float ss = d * d;
#pragma unroll
    for (int o = 16; o > 0; o >>= 1) ss += __shfl_down_sync(0xffffffffu, ss, o);
    __shared__ float ws[8];
    int lane = threadIdx.x & 31, warp = threadIdx.x >> 5;
    if (lane == 0) ws[warp] = ss;
    __syncthreads();
    if (threadIdx.x < 8) {
        float v = ws[threadIdx.x];
#pragma unroll
        for (int o = 4; o > 0; o >>= 1) v += __shfl_down_sync(0xffu, v, o);
        if (threadIdx.x == 0) atomicAdd(&g_accum, (double)v);
    }
}

// ---------------- perplexity + loss finalize ----------------
__global__ void final_kernel(float* __restrict__ out) {
    __shared__ float ws[8];
    int tid = threadIdx.x;
    float s = 0.f;
    for (int k = tid; k < K_CODES; k += 256) {
        float p = (float)g_hist[k] * (1.0f / N_ROWS);
        s += p * logf(p + 1e-10f);
    }
#pragma unroll
    for (int o = 16; o > 0; o >>= 1) s += __shfl_down_sync(0xffffffffu, s, o);
    int lane = tid & 31, warp = tid >> 5;
    if (lane == 0) ws[warp] = s;
    __syncthreads();
    if (tid < 8) {
        float v = ws[tid];
#pragma unroll
        for (int o = 4; o > 0; o >>= 1) v += __shfl_down_sync(0xffu, v, o);
        if (tid == 0) {
            out[OUT_EMB + N_ROWS]     = 0.25f * (float)(g_accum * (1.0 / 2097152.0));
            out[OUT_EMB + N_ROWS + 1] = expf(-v);
        }
    }
}

// ---------------- launch ----------------
extern "C" void kernel_launch(void* const* d_in, const int* in_sizes, int n_in,
                              void* d_out, int out_size) {
    const float* z = (const float*)d_in[0];
    const float* emb = (const float*)d_in[1];
    if (in_sizes[0] == K_CODES * C_DIM && in_sizes[1] == N_ROWS * C_DIM) {
        // defensive: swapped metadata order
        z = (const float*)d_in[1];
        emb = (const float*)d_in[0];
    }
    float* out = (float*)d_out;

    cudaFuncSetAttribute(vq_main, cudaFuncAttributeMaxDynamicSharedMemorySize,
                         196608);

    init_kernel<<<64, 256>>>();
    transpose_kernel<<<dim3(256, 8), dim3(32, 8)>>>(z);
    enorm_kernel<<<2048, 256>>>(emb);
    vq_main<<<dim3(64, 2), 256, 196608>>>(emb);
    merge_kernel<<<32, 256>>>();
    out_kernel<<<8192, 256>>>(z, emb, out);
    final_kernel<<<1, 256>>>(out);
}

// round 4
// speedup vs baseline: 1.7309x; 1.7309x over previous
#include <cuda_runtime.h>
#include <math.h>
#include <float.h>
#include <stdint.h>

#define N_ROWS   8192
#define C_DIM    256
#define K_CODES  16384
#define OUT_EMB  2097152

// ---------------- scratch (static, no allocations) ----------------
__device__ __align__(16) float g_zhi[N_ROWS * C_DIM];
__device__ __align__(16) float g_zlo[N_ROWS * C_DIM];
__device__ __align__(16) float g_ehi[K_CODES * C_DIM];
__device__ __align__(16) float g_elo[K_CODES * C_DIM];
__device__ __align__(16) float g_enorm[K_CODES];
__device__ unsigned long long g_best[N_ROWS];
__device__ int    g_idx[N_ROWS];
__device__ int    g_hist[K_CODES];
__device__ double g_accum;

// ---------------- PTX helpers (all compute_100-legal) ----------------
__device__ __forceinline__ uint32_t smem_u32(const void* p) {
    uint32_t a;
    asm("{ .reg .u64 t; cvta.to.shared.u64 t, %1; cvt.u32.u64 %0, t; }"
        : "=r"(a) : "l"(p));
    return a;
}
__device__ __forceinline__ void cp_async16(uint32_t saddr, const void* gaddr) {
    asm volatile("cp.async.cg.shared.global [%0], [%1], 16;\n"
                 :: "r"(saddr), "l"(gaddr));
}
__device__ __forceinline__ void cp_commit() {
    asm volatile("cp.async.commit_group;\n");
}
template <int N>
__device__ __forceinline__ void cp_wait() {
    asm volatile("cp.async.wait_group %0;\n" :: "n"(N));
}
__device__ __forceinline__ float to_tf32(float x) {
    uint32_t r;
    asm("cvt.rna.tf32.f32 %0, %1;" : "=r"(r) : "f"(x));
    return __uint_as_float(r);
}
__device__ __forceinline__ void ldsm4(uint32_t* r, uint32_t addr) {
    asm volatile("ldmatrix.sync.aligned.m8n8.x4.shared.b16 {%0,%1,%2,%3}, [%4];"
                 : "=r"(r[0]), "=r"(r[1]), "=r"(r[2]), "=r"(r[3]) : "r"(addr));
}
__device__ __forceinline__ void mma_tf32(float* d, const uint32_t* a,
                                         const uint32_t* b) {
    asm volatile(
        "mma.sync.aligned.m16n8k8.row.col.f32.tf32.tf32.f32 "
        "{%0,%1,%2,%3}, {%4,%5,%6,%7}, {%8,%9}, {%0,%1,%2,%3};"
        : "+f"(d[0]), "+f"(d[1]), "+f"(d[2]), "+f"(d[3])
        : "r"(a[0]), "r"(a[1]), "r"(a[2]), "r"(a[3]), "r"(b[0]), "r"(b[1]));
}

// ---------------- init ----------------
__global__ void init_kernel() {
    int t = blockIdx.x * blockDim.x + threadIdx.x;
    if (t < K_CODES) g_hist[t] = 0;
    if (t < N_ROWS) g_best[t] = 0xFFFFFFFFFFFFFFFFull;
    if (t == 0) g_accum = 0.0;
}

// ---------------- z [B,C,T,H,W] -> zhi/zlo [N, C] (tf32 split) ------
__global__ void split_z(const float* __restrict__ z) {
    __shared__ float s[32][33];
    int n0 = blockIdx.x * 32, c0 = blockIdx.y * 32;
    int tx = threadIdx.x, ty = threadIdx.y;
#pragma unroll
    for (int k = 0; k < 4; k++) {
        int yy = ty + k * 8;
        int c = c0 + yy;
        int n = n0 + tx;
        int b = n >> 11, thw = n & 2047;
        s[yy][tx] = z[((b * C_DIM + c) << 11) + thw];
    }
    __syncthreads();
#pragma unroll
    for (int k = 0; k < 4; k++) {
        int yy = ty + k * 8;
        float v = s[tx][yy];
        float hi = to_tf32(v);
        int o = (n0 + yy) * C_DIM + c0 + tx;
        g_zhi[o] = hi;
        g_zlo[o] = to_tf32(v - hi);
    }
}

// ---------------- emb -> ehi/elo (tf32 split) + ||e||^2 -------------
__global__ void split_e(const float* __restrict__ emb) {
    int w = (blockIdx.x * blockDim.x + threadIdx.x) >> 5;
    int lane = threadIdx.x & 31;
    if (w >= K_CODES) return;
    const float4* e4 = (const float4*)(emb + (size_t)w * C_DIM);
    float4* h4 = (float4*)(g_ehi + (size_t)w * C_DIM);
    float4* l4 = (float4*)(g_elo + (size_t)w * C_DIM);
    float s = 0.f;
#pragma unroll
    for (int q = 0; q < 2; q++) {
        float4 v = e4[q * 32 + lane];
        s += v.x * v.x + v.y * v.y + v.z * v.z + v.w * v.w;
        float4 h, l;
        h.x = to_tf32(v.x); l.x = to_tf32(v.x - h.x);
        h.y = to_tf32(v.y); l.y = to_tf32(v.y - h.y);
        h.z = to_tf32(v.z); l.z = to_tf32(v.z - h.z);
        h.w = to_tf32(v.w); l.w = to_tf32(v.w - h.w);
        h4[q * 32 + lane] = h;
        l4[q * 32 + lane] = l;
    }
#pragma unroll
    for (int o = 16; o > 0; o >>= 1) s += __shfl_down_sync(0xffffffffu, s, o);
    if (lane == 0) g_enorm[w] = s;
}

// ---------------- fused 3xTF32 mma.sync GEMM + argmin ---------------
// CTA tile 128(M) x 256(N); 8 warps as 2(M) x 4(N); warp tile 64x64.
// K pipelined in 8 chunks of 32 (cp.async double buffer).
// stage: Ahi 16K | Alo 16K | Bhi 32K | Blo 32K = 96K; x2 stages = 192K.
#define STAGE_BYTES 98304
#define CTRL_OFF    196608
#define SMEM_TOTAL  201728

__global__ void __launch_bounds__(256, 1)
vq_gemm() {
    extern __shared__ __align__(1024) char smem[];
    const uint32_t sb = smem_u32(smem);
    const int tid = threadIdx.x;
    const int wid = tid >> 5, l = tid & 31;
    const int warpM = wid >> 2, warpN = wid & 3;
    const int m0 = blockIdx.x << 7;
    const int n0 = blockIdx.y << 8;

    float* enorm_s = (float*)(smem + CTRL_OFF);          // 1024 B
    float* rv = (float*)(smem + CTRL_OFF + 1024);        // 2048 B
    int*   ri = (int*)(smem + CTRL_OFF + 3072);          // 2048 B

    enorm_s[tid] = g_enorm[n0 + tid];

    // per-thread ldmatrix row precompute
    uint32_t aoff[4], boff[4];
    int a7[4], b7[4];
#pragma unroll
    for (int mt = 0; mt < 4; mt++) {
        int row = warpM * 64 + mt * 16 + ((l >> 3) & 1) * 8 + (l & 7);
        aoff[mt] = (uint32_t)(row * 128);
        a7[mt] = row & 7;
    }
#pragma unroll
    for (int ntp = 0; ntp < 4; ntp++) {
        int row = warpN * 64 + ntp * 16 + ((l >> 4) & 1) * 8 + (l & 7);
        boff[ntp] = (uint32_t)(row * 128);
        b7[ntp] = row & 7;
    }
    const int segAb = (l >> 4);
    const int segBb = (l >> 3) & 1;

    // ---- chunk loader: k in [32c, 32c+32) -> stage (cp.async, swizzled) ----
    auto load_chunk = [&](int c, int stage) {
        const uint32_t base = sb + stage * STAGE_BYTES;
        const int k0 = c * 32;
#pragma unroll
        for (int q = 0; q < 4; q++) {
            int idx = q * 256 + tid;
            int row = idx >> 3, seg = idx & 7;
            uint32_t so = (uint32_t)(row * 128 + ((seg ^ (row & 7)) << 4));
            size_t go = (size_t)(m0 + row) * C_DIM + k0 + seg * 4;
            cp_async16(base + so,         g_zhi + go);
            cp_async16(base + 16384 + so, g_zlo + go);
        }
#pragma unroll
        for (int q = 0; q < 8; q++) {
            int idx = q * 256 + tid;
            int row = idx >> 3, seg = idx & 7;
            uint32_t so = (uint32_t)(row * 128 + ((seg ^ (row & 7)) << 4));
            size_t go = (size_t)(n0 + row) * C_DIM + k0 + seg * 4;
            cp_async16(base + 32768 + so, g_ehi + go);
            cp_async16(base + 65536 + so, g_elo + go);
        }
        cp_commit();
    };

    float acc[4][8][4];
#pragma unroll
    for (int mt = 0; mt < 4; mt++)
#pragma unroll
        for (int nt = 0; nt < 8; nt++)
#pragma unroll
            for (int r = 0; r < 4; r++) acc[mt][nt][r] = 0.f;

    load_chunk(0, 0);
    load_chunk(1, 1);

    for (int t = 0; t < 8; t++) {
        if (t < 7) cp_wait<1>(); else cp_wait<0>();
        __syncthreads();
        const uint32_t base = sb + (t & 1) * STAGE_BYTES;

#pragma unroll
        for (int ks = 0; ks < 4; ks++) {
            uint32_t Ah[4][4], Al[4][4];
            const int sA = 2 * ks + segAb;
#pragma unroll
            for (int mt = 0; mt < 4; mt++) {
                uint32_t ad = base + aoff[mt] + (uint32_t)((sA ^ a7[mt]) << 4);
                ldsm4(Ah[mt], ad);
                ldsm4(Al[mt], ad + 16384);
            }
            const int sB = 2 * ks + segBb;
#pragma unroll
            for (int h = 0; h < 2; h++) {
                uint32_t Bh[2][4], Bl[2][4];
#pragma unroll
                for (int p = 0; p < 2; p++) {
                    int ntp = h * 2 + p;
                    uint32_t bd = base + 32768 + boff[ntp] +
                                  (uint32_t)((sB ^ b7[ntp]) << 4);
                    ldsm4(Bh[p], bd);
                    ldsm4(Bl[p], bd + 32768);
                }
#pragma unroll
                for (int p = 0; p < 2; p++)
#pragma unroll
                    for (int sub = 0; sub < 2; sub++) {
                        int nt = h * 4 + p * 2 + sub;
#pragma unroll
                        for (int mt = 0; mt < 4; mt++) {
                            mma_tf32(acc[mt][nt], Ah[mt], &Bh[p][sub * 2]);
                            mma_tf32(acc[mt][nt], Ah[mt], &Bl[p][sub * 2]);
                            mma_tf32(acc[mt][nt], Al[mt], &Bh[p][sub * 2]);
                        }
                    }
            }
        }
        __syncthreads();
        if (t + 2 < 8) load_chunk(t + 2, t & 1);
    }

    // ---- epilogue: distances + per-row argmin ----
#pragma unroll
    for (int s = 0; s < 8; s++) {
        const int mt = s >> 1, half = s & 1;
        const int rloc = warpM * 64 + mt * 16 + half * 8 + (l >> 2);
        float bv = INFINITY;
        int bi = 0;
#pragma unroll
        for (int nt = 0; nt < 8; nt++)
#pragma unroll
            for (int j = 0; j < 2; j++) {
                int cl = warpN * 64 + nt * 8 + 2 * (l & 3) + j;
                float d = enorm_s[cl] - 2.0f * acc[mt][nt][half * 2 + j];
                if (d < bv) { bv = d; bi = n0 + cl; }
            }
#pragma unroll
        for (int off = 1; off <= 2; off <<= 1) {
            float ov = __shfl_xor_sync(0xffffffffu, bv, off);
            int   oi = __shfl_xor_sync(0xffffffffu, bi, off);
            if (ov < bv || (ov == bv && oi < bi)) { bv = ov; bi = oi; }
        }
        if ((l & 3) == 0) {
            rv[warpN * 128 + rloc] = bv;
            ri[warpN * 128 + rloc] = bi;
        }
    }
    __syncthreads();
    if (tid < 128) {
        float bv = rv[tid];
        int bi = ri[tid];
#pragma unroll
        for (int w = 1; w < 4; w++) {
            float v = rv[w * 128 + tid];
            int i2 = ri[w * 128 + tid];
            if (v < bv || (v == bv && i2 < bi)) { bv = v; bi = i2; }
        }
        unsigned u = __float_as_uint(bv);
        u = (u & 0x80000000u) ? ~u : (u | 0x80000000u);
        unsigned long long key = ((unsigned long long)u << 32) | (unsigned)bi;
        atomicMin(&g_best[m0 + tid], key);
    }
}

// ---------------- merge best -> idx + histogram ----------------
__global__ void merge_kernel() {
    int n = blockIdx.x * blockDim.x + threadIdx.x;
    if (n >= N_ROWS) return;
    int idx = (int)(g_best[n] & 0xFFFFFFFFull);
    g_idx[n] = idx;
    atomicAdd(&g_hist[idx], 1);
}

// ---------------- gather + channels-first output + loss ----------
__global__ void out_kernel(const float* __restrict__ z,
                           const float* __restrict__ emb,
                           float* __restrict__ out) {
    int i = blockIdx.x * blockDim.x + threadIdx.x;
    int b = i >> 19;
    int rem = i & 524287;
    int c = rem >> 11;
    int thw = rem & 2047;
    int n = (b << 11) | thw;
    int idx = g_idx[n];
    float e = emb[(size_t)idx * C_DIM + c];
    out[i] = e;
    if (c == 0) out[OUT_EMB + n] = (float)idx;
    float d = z[i] - e;
    float ss = d * d;
#pragma unroll
    for (int o = 16; o > 0; o >>= 1) ss += __shfl_down_sync(0xffffffffu, ss, o);
    __shared__ float ws[8];
    int lane = threadIdx.x & 31, warp = threadIdx.x >> 5;
    if (lane == 0) ws[warp] = ss;
    __syncthreads();
    if (threadIdx.x < 8) {
        float v = ws[threadIdx.x];
#pragma unroll
        for (int o = 4; o > 0; o >>= 1) v += __shfl_down_sync(0xffu, v, o);
        if (threadIdx.x == 0) atomicAdd(&g_accum, (double)v);
    }
}

// ---------------- perplexity + loss finalize ----------------
__global__ void final_kernel(float* __restrict__ out) {
    __shared__ float ws[8];
    int tid = threadIdx.x;
    float s = 0.f;
    for (int k = tid; k < K_CODES; k += 256) {
        float p = (float)g_hist[k] * (1.0f / N_ROWS);
        s += p * logf(p + 1e-10f);
    }
#pragma unroll
    for (int o = 16; o > 0; o >>= 1) s += __shfl_down_sync(0xffffffffu, s, o);
    int lane = tid & 31, warp = tid >> 5;
    if (lane == 0) ws[warp] = s;
    __syncthreads();
    if (tid < 8) {
        float v = ws[tid];
#pragma unroll
        for (int o = 4; o > 0; o >>= 1) v += __shfl_down_sync(0xffu, v, o);
        if (tid == 0) {
            out[OUT_EMB + N_ROWS]     = 0.25f * (float)(g_accum * (1.0 / 2097152.0));
            out[OUT_EMB + N_ROWS + 1] = expf(-v);
        }
    }
}

// ---------------- launch ----------------
extern "C" void kernel_launch(void* const* d_in, const int* in_sizes, int n_in,
                              void* d_out, int out_size) {
    const float* z = (const float*)d_in[0];
    const float* emb = (const float*)d_in[1];
    if (in_sizes[0] == K_CODES * C_DIM && in_sizes[1] == N_ROWS * C_DIM) {
        z = (const float*)d_in[1];
        emb = (const float*)d_in[0];
    }
    float* out = (float*)d_out;

    cudaFuncSetAttribute(vq_gemm, cudaFuncAttributeMaxDynamicSharedMemorySize,
                         SMEM_TOTAL);

    init_kernel<<<64, 256>>>();
    split_z<<<dim3(256, 8), dim3(32, 8)>>>(z);
    split_e<<<2048, 256>>>(emb);
    vq_gemm<<<dim3(64, 64), 256, SMEM_TOTAL>>>();
    merge_kernel<<<32, 256>>>();
    out_kernel<<<8192, 256>>>(z, emb, out);
    final_kernel<<<1, 256>>>(out);
}

// round 5
// speedup vs baseline: 2.7697x; 1.6002x over previous
#include <cuda_runtime.h>
#include <cuda_fp16.h>
#include <math.h>
#include <float.h>
#include <stdint.h>

#define N_ROWS   8192
#define C_DIM    256
#define K_CODES  16384
#define OUT_EMB  2097152

// ---------------- scratch (static, no allocations) ----------------
__device__ __align__(16) __half g_zhi[N_ROWS * C_DIM];
__device__ __align__(16) __half g_zlo[N_ROWS * C_DIM];
__device__ __align__(16) __half g_ehi[K_CODES * C_DIM];
__device__ __align__(16) __half g_elo[K_CODES * C_DIM];
__device__ __align__(16) float g_enorm[K_CODES];
__device__ unsigned long long g_best[N_ROWS];
__device__ int    g_idx[N_ROWS];
__device__ int    g_hist[K_CODES];
__device__ double g_accum;

// ---------------- PTX helpers (compute_100-legal) ----------------
__device__ __forceinline__ uint32_t smem_u32(const void* p) {
    uint32_t a;
    asm("{ .reg .u64 t; cvta.to.shared.u64 t, %1; cvt.u32.u64 %0, t; }"
        : "=r"(a) : "l"(p));
    return a;
}
__device__ __forceinline__ void cp_async16(uint32_t saddr, const void* gaddr) {
    asm volatile("cp.async.cg.shared.global [%0], [%1], 16;\n"
                 :: "r"(saddr), "l"(gaddr));
}
__device__ __forceinline__ void cp_commit() {
    asm volatile("cp.async.commit_group;\n");
}
template <int N>
__device__ __forceinline__ void cp_wait() {
    asm volatile("cp.async.wait_group %0;\n" :: "n"(N));
}
__device__ __forceinline__ void ldsm4(uint32_t* r, uint32_t addr) {
    asm volatile("ldmatrix.sync.aligned.m8n8.x4.shared.b16 {%0,%1,%2,%3}, [%4];"
                 : "=r"(r[0]), "=r"(r[1]), "=r"(r[2]), "=r"(r[3]) : "r"(addr));
}
__device__ __forceinline__ void mma_f16(float* d, const uint32_t* a,
                                        uint32_t b0, uint32_t b1) {
    asm volatile(
        "mma.sync.aligned.m16n8k16.row.col.f32.f16.f16.f32 "
        "{%0,%1,%2,%3}, {%4,%5,%6,%7}, {%8,%9}, {%0,%1,%2,%3};"
        : "+f"(d[0]), "+f"(d[1]), "+f"(d[2]), "+f"(d[3])
        : "r"(a[0]), "r"(a[1]), "r"(a[2]), "r"(a[3]), "r"(b0), "r"(b1));
}

// ---------------- init ----------------
__global__ void init_kernel() {
    int t = blockIdx.x * blockDim.x + threadIdx.x;
    if (t < K_CODES) g_hist[t] = 0;
    if (t < N_ROWS) g_best[t] = 0xFFFFFFFFFFFFFFFFull;
    if (t == 0) g_accum = 0.0;
}

// ---------------- z [B,C,T,H,W] -> zhi/zlo [N, C] (fp16 split) ------
__global__ void split_z(const float* __restrict__ z) {
    __shared__ float s[32][33];
    int n0 = blockIdx.x * 32, c0 = blockIdx.y * 32;
    int tx = threadIdx.x, ty = threadIdx.y;
#pragma unroll
    for (int k = 0; k < 4; k++) {
        int yy = ty + k * 8;
        int c = c0 + yy;
        int n = n0 + tx;
        int b = n >> 11, thw = n & 2047;
        s[yy][tx] = z[((b * C_DIM + c) << 11) + thw];
    }
    __syncthreads();
#pragma unroll
    for (int k = 0; k < 4; k++) {
        int yy = ty + k * 8;
        float v = s[tx][yy];
        __half hi = __float2half_rn(v);
        float lo = v - __half2float(hi);
        int o = (n0 + yy) * C_DIM + c0 + tx;
        g_zhi[o] = hi;
        g_zlo[o] = __float2half_rn(lo);
    }
}

// ---------------- emb -> ehi/elo (fp16 split) + ||e||^2 -------------
__global__ void split_e(const float* __restrict__ emb) {
    int w = (blockIdx.x * blockDim.x + threadIdx.x) >> 5;
    int lane = threadIdx.x & 31;
    if (w >= K_CODES) return;
    const float4* e4 = (const float4*)(emb + (size_t)w * C_DIM);
    __half2* h2 = (__half2*)(g_ehi + (size_t)w * C_DIM);
    __half2* l2 = (__half2*)(g_elo + (size_t)w * C_DIM);
    float s = 0.f;
#pragma unroll
    for (int q = 0; q < 2; q++) {
        float4 v = e4[q * 32 + lane];
        s += v.x * v.x + v.y * v.y + v.z * v.z + v.w * v.w;
        __half hx = __float2half_rn(v.x), hy = __float2half_rn(v.y);
        __half hz = __float2half_rn(v.z), hw = __float2half_rn(v.w);
        __half lx = __float2half_rn(v.x - __half2float(hx));
        __half ly = __float2half_rn(v.y - __half2float(hy));
        __half lz = __float2half_rn(v.z - __half2float(hz));
        __half lw = __float2half_rn(v.w - __half2float(hw));
        h2[(q * 32 + lane) * 2 + 0] = __halves2half2(hx, hy);
        h2[(q * 32 + lane) * 2 + 1] = __halves2half2(hz, hw);
        l2[(q * 32 + lane) * 2 + 0] = __halves2half2(lx, ly);
        l2[(q * 32 + lane) * 2 + 1] = __halves2half2(lz, lw);
    }
#pragma unroll
    for (int o = 16; o > 0; o >>= 1) s += __shfl_down_sync(0xffffffffu, s, o);
    if (lane == 0) g_enorm[w] = s;
}

// ---------------- fused 3xFP16 mma.sync GEMM + argmin ---------------
// CTA tile 128(M) x 256(N); 8 warps 2(M) x 4(N); warp tile 64x64.
// K pipelined in 4 chunks of 64 (cp.async double buffer).
// stage: Ahi 16K | Alo 16K | Bhi 32K | Blo 32K = 96K; x2 = 192K.
#define STAGE_BYTES 98304
#define CTRL_OFF    196608
#define SMEM_TOTAL  201728

__global__ void __launch_bounds__(256, 1)
vq_gemm() {
    extern __shared__ __align__(1024) char smem[];
    const uint32_t sb = smem_u32(smem);
    const int tid = threadIdx.x;
    const int wid = tid >> 5, l = tid & 31;
    const int warpM = wid >> 2, warpN = wid & 3;
    const int m0 = blockIdx.x << 7;
    const int n0 = blockIdx.y << 8;

    float* enorm_s = (float*)(smem + CTRL_OFF);          // 1024 B
    float* rv = (float*)(smem + CTRL_OFF + 1024);        // 2048 B
    int*   ri = (int*)(smem + CTRL_OFF + 3072);          // 2048 B

    enorm_s[tid] = g_enorm[n0 + tid];

    // ldmatrix x4 lane address pattern (identical structure for A and B):
    // lanes 0-7:  tile row 0-7,  k-seg low   lanes 8-15: rows 8-15, seg low
    // lanes16-23: rows 0-7, seg high         lanes24-31: rows 8-15, seg high
    uint32_t aoff[4], boff[4];
    int a7[4], b7[4];
#pragma unroll
    for (int mt = 0; mt < 4; mt++) {
        int row = warpM * 64 + mt * 16 + ((l >> 3) & 1) * 8 + (l & 7);
        aoff[mt] = (uint32_t)(row * 128);
        a7[mt] = row & 7;
    }
#pragma unroll
    for (int ntp = 0; ntp < 4; ntp++) {
        int row = warpN * 64 + ntp * 16 + ((l >> 3) & 1) * 8 + (l & 7);
        boff[ntp] = (uint32_t)(row * 128);
        b7[ntp] = row & 7;
    }
    const int segbit = l >> 4;   // 0 for k0-7 halves, 1 for k8-15 (within k16 step)

    // ---- chunk loader: k halves [64c, 64c+64) -> stage (cp.async) ----
    auto load_chunk = [&](int c, int stage) {
        const uint32_t base = sb + stage * STAGE_BYTES;
        const int k0 = c * 64;
#pragma unroll
        for (int q = 0; q < 4; q++) {       // A: 128 rows x 128 B per array
            int idx = q * 256 + tid;
            int row = idx >> 3, seg = idx & 7;
            uint32_t so = (uint32_t)(row * 128 + ((seg ^ (row & 7)) << 4));
            size_t go = (size_t)(m0 + row) * C_DIM + k0 + seg * 8;
            cp_async16(base + so,         g_zhi + go);
            cp_async16(base + 16384 + so, g_zlo + go);
        }
#pragma unroll
        for (int q = 0; q < 8; q++) {       // B: 256 rows x 128 B per array
            int idx = q * 256 + tid;
            int row = idx >> 3, seg = idx & 7;
            uint32_t so = (uint32_t)(row * 128 + ((seg ^ (row & 7)) << 4));
            size_t go = (size_t)(n0 + row) * C_DIM + k0 + seg * 8;
            cp_async16(base + 32768 + so, g_ehi + go);
            cp_async16(base + 65536 + so, g_elo + go);
        }
        cp_commit();
    };

    float acc[4][8][4];
#pragma unroll
    for (int mt = 0; mt < 4; mt++)
#pragma unroll
        for (int nt = 0; nt < 8; nt++)
#pragma unroll
            for (int r = 0; r < 4; r++) acc[mt][nt][r] = 0.f;

    load_chunk(0, 0);
    load_chunk(1, 1);

    for (int t = 0; t < 4; t++) {
        if (t < 3) cp_wait<1>(); else cp_wait<0>();
        __syncthreads();
        const uint32_t base = sb + (t & 1) * STAGE_BYTES;

#pragma unroll
        for (int ks = 0; ks < 4; ks++) {            // k16 steps within chunk64
            const int seg = 2 * ks + segbit;        // 16-byte segment index
            uint32_t Ah[4][4], Al[4][4];
#pragma unroll
            for (int mt = 0; mt < 4; mt++) {
                uint32_t ad = base + aoff[mt] + (uint32_t)((seg ^ a7[mt]) << 4);
                ldsm4(Ah[mt], ad);
                ldsm4(Al[mt], ad + 16384);
            }
#pragma unroll
            for (int ntp = 0; ntp < 4; ntp++) {
                uint32_t Bh[4], Bl[4];
                uint32_t bd = base + 32768 + boff[ntp] +
                              (uint32_t)((seg ^ b7[ntp]) << 4);
                ldsm4(Bh, bd);
                ldsm4(Bl, bd + 32768);
                // r0=(n0-7,k0-7) r1=(n8-15,k0-7) r2=(n0-7,k8-15) r3=(n8-15,k8-15)
#pragma unroll
                for (int sub = 0; sub < 2; sub++) {
                    int nt = ntp * 2 + sub;
#pragma unroll
                    for (int mt = 0; mt < 4; mt++) {
                        mma_f16(acc[mt][nt], Ah[mt], Bh[sub], Bh[sub + 2]);
                        mma_f16(acc[mt][nt], Ah[mt], Bl[sub], Bl[sub + 2]);
                        mma_f16(acc[mt][nt], Al[mt], Bh[sub], Bh[sub + 2]);
                    }
                }
            }
        }
        __syncthreads();
        if (t + 2 < 4) load_chunk(t + 2, t & 1);
    }

    // ---- epilogue: distances + per-row argmin ----
#pragma unroll
    for (int s = 0; s < 8; s++) {
        const int mt = s >> 1, half = s & 1;
        const int rloc = warpM * 64 + mt * 16 + half * 8 + (l >> 2);
        float bv = INFINITY;
        int bi = 0;
#pragma unroll
        for (int nt = 0; nt < 8; nt++)
#pragma unroll
            for (int j = 0; j < 2; j++) {
                int cl = warpN * 64 + (nt >> 1) * 16 + (nt & 1) * 8 +
                         2 * (l & 3) + j;
                float d = enorm_s[cl] - 2.0f * acc[mt][nt][half * 2 + j];
                if (d < bv) { bv = d; bi = n0 + cl; }
            }
#pragma unroll
        for (int off = 1; off <= 2; off <<= 1) {
            float ov = __shfl_xor_sync(0xffffffffu, bv, off);
            int   oi = __shfl_xor_sync(0xffffffffu, bi, off);
            if (ov < bv || (ov == bv && oi < bi)) { bv = ov; bi = oi; }
        }
        if ((l & 3) == 0) {
            rv[warpN * 128 + rloc] = bv;
            ri[warpN * 128 + rloc] = bi;
        }
    }
    __syncthreads();
    if (tid < 128) {
        float bv = rv[tid];
        int bi = ri[tid];
#pragma unroll
        for (int w = 1; w < 4; w++) {
            float v = rv[w * 128 + tid];
            int i2 = ri[w * 128 + tid];
            if (v < bv || (v == bv && i2 < bi)) { bv = v; bi = i2; }
        }
        unsigned u = __float_as_uint(bv);
        u = (u & 0x80000000u) ? ~u : (u | 0x80000000u);
        unsigned long long key = ((unsigned long long)u << 32) | (unsigned)bi;
        atomicMin(&g_best[m0 + tid], key);
    }
}

// ---------------- merge best -> idx + histogram ----------------
__global__ void merge_kernel() {
    int n = blockIdx.x * blockDim.x + threadIdx.x;
    if (n >= N_ROWS) return;
    int idx = (int)(g_best[n] & 0xFFFFFFFFull);
    g_idx[n] = idx;
    atomicAdd(&g_hist[idx], 1);
}

// ---------------- gather + channels-first output + loss ----------
__global__ void out_kernel(const float* __restrict__ z,
                           const float* __restrict__ emb,
                           float* __restrict__ out) {
    int i = blockIdx.x * blockDim.x + threadIdx.x;
    int b = i >> 19;
    int rem = i & 524287;
    int c = rem >> 11;
    int thw = rem & 2047;
    int n = (b << 11) | thw;
    int idx = g_idx[n];
    float e = emb[(size_t)idx * C_DIM + c];
    out[i] = e;
    if (c == 0) out[OUT_EMB + n] = (float)idx;
    float d = z[i] - e;
    float ss = d * d;
#pragma unroll
    for (int o = 16; o > 0; o >>= 1) ss += __shfl_down_sync(0xffffffffu, ss, o);
    __shared__ float ws[8];
    int lane = threadIdx.x & 31, warp = threadIdx.x >> 5;
    if (lane == 0) ws[warp] = ss;
    __syncthreads();
    if (threadIdx.x < 8) {
        float v = ws[threadIdx.x];
#pragma unroll
        for (int o = 4; o > 0; o >>= 1) v += __shfl_down_sync(0xffu, v, o);
        if (threadIdx.x == 0) atomicAdd(&g_accum, (double)v);
    }
}

// ---------------- perplexity + loss finalize ----------------
__global__ void final_kernel(float* __restrict__ out) {
    __shared__ float ws[8];
    int tid = threadIdx.x;
    float s = 0.f;
    for (int k = tid; k < K_CODES; k += 256) {
        float p = (float)g_hist[k] * (1.0f / N_ROWS);
        s += p * logf(p + 1e-10f);
    }
#pragma unroll
    for (int o = 16; o > 0; o >>= 1) s += __shfl_down_sync(0xffffffffu, s, o);
    int lane = tid & 31, warp = tid >> 5;
    if (lane == 0) ws[warp] = s;
    __syncthreads();
    if (tid < 8) {
        float v = ws[tid];
#pragma unroll
        for (int o = 4; o > 0; o >>= 1) v += __shfl_down_sync(0xffu, v, o);
        if (tid == 0) {
            out[OUT_EMB + N_ROWS]     = 0.25f * (float)(g_accum * (1.0 / 2097152.0));
            out[OUT_EMB + N_ROWS + 1] = expf(-v);
        }
    }
}

// ---------------- launch ----------------
extern "C" void kernel_launch(void* const* d_in, const int* in_sizes, int n_in,
                              void* d_out, int out_size) {
    const float* z = (const float*)d_in[0];
    const float* emb = (const float*)d_in[1];
    if (in_sizes[0] == K_CODES * C_DIM && in_sizes[1] == N_ROWS * C_DIM) {
        z = (const float*)d_in[1];
        emb = (const float*)d_in[0];
    }
    float* out = (float*)d_out;

    cudaFuncSetAttribute(vq_gemm, cudaFuncAttributeMaxDynamicSharedMemorySize,
                         SMEM_TOTAL);

    init_kernel<<<64, 256>>>();
    split_z<<<dim3(256, 8), dim3(32, 8)>>>(z);
    split_e<<<2048, 256>>>(emb);
    vq_gemm<<<dim3(64, 64), 256, SMEM_TOTAL>>>();
    merge_kernel<<<32, 256>>>();
    out_kernel<<<8192, 256>>>(z, emb, out);
    final_kernel<<<1, 256>>>(out);
}